// round 8
// baseline (speedup 1.0000x reference)
#include <cuda_runtime.h>

constexpr int Wd = 1024, Hd = 1024;
constexpr long HW = (long)Wd * Hd;
constexpr int CIN = 18;
constexpr float L2E = 1.4426950408889634f;

// Tile: 8 ch x 14 rows x 136 cols = 60,928 B. Params: 32 u64-slots x 256 thr = 32,768 B.
constexpr int TP   = 136;
constexpr int TROW = 14;                   // 8 output rows + 6 halo
constexpr int TCH  = TROW * TP;            // 1904 floats
constexpr int TILE_BYTES  = 8 * TCH * 4;   // 60,928
constexpr int SMEM_BYTES  = TILE_BYTES + 32 * 256 * 8;   // 93,696

using u64 = unsigned long long;

__device__ __forceinline__ u64 pack2(float lo, float hi) {
    u64 r; asm("mov.b64 %0,{%1,%2};" : "=l"(r) : "f"(lo), "f"(hi)); return r;
}
__device__ __forceinline__ void unpack2(u64 v, float& lo, float& hi) {
    asm("mov.b64 {%0,%1},%2;" : "=f"(lo), "=f"(hi) : "l"(v));
}
__device__ __forceinline__ u64 fma2(u64 a, u64 b, u64 c) {
    u64 d; asm("fma.rn.f32x2 %0,%1,%2,%3;" : "=l"(d) : "l"(a), "l"(b), "l"(c)); return d;
}
__device__ __forceinline__ u64 add2(u64 a, u64 b) {
    u64 d; asm("add.rn.f32x2 %0,%1,%2;" : "=l"(d) : "l"(a), "l"(b)); return d;
}
__device__ __forceinline__ float ex2(float x) {
    float r; asm("ex2.approx.f32 %0,%1;" : "=f"(r) : "f"(x)); return r;
}
__device__ __forceinline__ u64 bcast2(float x) {
    unsigned u = __float_as_uint(x); return ((u64)u << 32) | u;
}

// ---------------------------------------------------------------------------
// Interior: block = 32 x-groups (4 px) x 8 rows. Neighbor data register-
// resident via tile LDS.128 + on-the-fly packs (the R6 winner). Per-pixel
// range params offloaded to per-thread smem slots to cut regs 168 -> ~115
// so 2 blocks (16 warps) fit per SM.
// ---------------------------------------------------------------------------
__device__ __forceinline__ void interior_path(const float* __restrict__ in,
                                              float* __restrict__ out,
                                              float* __restrict__ tile,
                                              u64* __restrict__ prm,
                                              int bx, int byi, int bz)
{
    const int g   = threadIdx.x;                 // 0..31
    const int ty  = threadIdx.y;                 // 0..7
    const int tid = ty * 32 + g;
    const int gxg = bx * 32 + g;
    const int x0  = 4 + gxg * 4;
    const int y   = 3 + byi * 8 + ty;

    const float* base = in + (long)bz * CIN * HW;

    // ---- Stage the 8 filterable channels into the tile (all 256 threads) ----
    {
        const int tx0 = bx * 128;
        const int gy0 = byi * 8;
        // 8ch * 14 rows * 34 float4 = 3808 slots
        for (int idx = tid; idx < 3808; idx += 256) {
            const int row = idx / 34;            // 0..111
            const int k   = idx - row * 34;      // 0..33
            const int c   = row / TROW;
            const int r   = row - c * TROW;
            int gx = tx0 + k * 4; if (gx > 1020) gx = 1020;   // clamped region unused
            int gy = gy0 + r;     if (gy > 1023) gy = 1023;   // clamped region unused
            float4 v = *(const float4*)(base + c * HW + (long)gy * Wd + gx);
            *(float4*)(tile + c * TCH + r * TP + k * 4) = v;
        }
    }
    __syncthreads();
    if (gxg > 253 || y > 1020) return;

    const long ctr = (long)y * Wd + x0;

    // ---- Params: compute once, park in per-thread smem slots (own slot only) ----
    u64 K2[2], sxl2[2], syl2[2];
    {
        float Ks[4] = {0.f, 0.f, 0.f, 0.f};
        #pragma unroll
        for (int c = 0; c < 8; ++c) {
            float4 fv = *(const float4*)(tile + c * TCH + (ty + 3) * TP + g * 4 + 4);
            float4 pv = *(const float4*)(base + (8 + c) * HW + ctr);
            const float f4[4] = {fv.x, fv.y, fv.z, fv.w};
            const float p4[4] = {pv.x, pv.y, pv.z, pv.w};
            float rs[4], ms[4];
            #pragma unroll
            for (int p = 0; p < 4; ++p) {
                float r = -(p4[p] * p4[p]) * L2E;        // log2(e) folded in
                rs[p] = r;
                ms[p] = -2.f * r * f4[p];
                Ks[p] = fmaf(r * f4[p], f4[p], Ks[p]);
            }
            prm[(c * 4 + 0) * 256 + tid] = pack2(rs[0], rs[1]);
            prm[(c * 4 + 1) * 256 + tid] = pack2(rs[2], rs[3]);
            prm[(c * 4 + 2) * 256 + tid] = pack2(ms[0], ms[1]);
            prm[(c * 4 + 3) * 256 + tid] = pack2(ms[2], ms[3]);
        }
        K2[0] = pack2(Ks[0], Ks[1]); K2[1] = pack2(Ks[2], Ks[3]);
        float4 sv = *(const float4*)(base + 16 * HW + ctr);
        float4 tv = *(const float4*)(base + 17 * HW + ctr);
        sxl2[0] = pack2(-(sv.x*sv.x)*L2E, -(sv.y*sv.y)*L2E);
        sxl2[1] = pack2(-(sv.z*sv.z)*L2E, -(sv.w*sv.w)*L2E);
        syl2[0] = pack2(-(tv.x*tv.x)*L2E, -(tv.y*tv.y)*L2E);
        syl2[1] = pack2(-(tv.z*tv.z)*L2E, -(tv.w*tv.w)*L2E);
    }

    u64 acc2[3][2] = {}, ws2[2] = {};
    const int rowoff0 = ty * TP + g * 4;

    #pragma unroll 1       // keep body inside I$ L1.5
    for (int i = 0; i < 7; ++i) {
        const int ro = rowoff0 + i * TP;
        const u64 dyb = bcast2((float)((i - 3) * (i - 3)));

        u64 s2[7][2];
        {
            const u64 kd0 = fma2(syl2[0], dyb, K2[0]);
            const u64 kd1 = fma2(syl2[1], dyb, K2[1]);
            #pragma unroll
            for (int j = 0; j < 7; ++j) { s2[j][0] = kd0; s2[j][1] = kd1; }
        }

        #pragma unroll
        for (int c = 0; c < 8; ++c) {
            const u64 rp0 = prm[(c * 4 + 0) * 256 + tid];
            const u64 rp1 = prm[(c * 4 + 1) * 256 + tid];
            const u64 mf0 = prm[(c * 4 + 2) * 256 + tid];
            const u64 mf1 = prm[(c * 4 + 3) * 256 + tid];
            const float* r0 = tile + c * TCH + ro;
            float4 v0 = *(const float4*)(r0);
            float4 v1 = *(const float4*)(r0 + 4);
            float4 v2 = *(const float4*)(r0 + 8);
            const float nv[12] = {v0.x, v0.y, v0.z, v0.w,
                                  v1.x, v1.y, v1.z, v1.w,
                                  v2.x, v2.y, v2.z, v2.w};
            #pragma unroll
            for (int j = 0; j < 7; ++j) {
                u64 a = pack2(nv[j + 1], nv[j + 2]);
                u64 b = pack2(nv[j + 3], nv[j + 4]);
                // s += fn * (rp*fn + mf)   (Horner)
                s2[j][0] = fma2(a, fma2(rp0, a, mf0), s2[j][0]);
                s2[j][1] = fma2(b, fma2(rp1, b, mf1), s2[j][1]);
            }
        }

        // Weights
        u64 w2a[7][2];
        #pragma unroll
        for (int j = 0; j < 7; ++j) {
            const u64 dxb = bcast2((float)((j - 3) * (j - 3)));
            #pragma unroll
            for (int pp = 0; pp < 2; ++pp) {
                u64 lw2 = fma2(sxl2[pp], dxb, s2[j][pp]);
                float a, b; unpack2(lw2, a, b);
                u64 w2 = pack2(ex2(a), ex2(b));
                w2a[j][pp] = w2;
                ws2[pp] = add2(ws2[pp], w2);
            }
        }

        // Accumulate output channels
        #pragma unroll
        for (int c = 0; c < 3; ++c) {
            const float* r0 = tile + c * TCH + ro;
            float4 v0 = *(const float4*)(r0);
            float4 v1 = *(const float4*)(r0 + 4);
            float4 v2 = *(const float4*)(r0 + 8);
            const float nv[12] = {v0.x, v0.y, v0.z, v0.w,
                                  v1.x, v1.y, v1.z, v1.w,
                                  v2.x, v2.y, v2.z, v2.w};
            #pragma unroll
            for (int j = 0; j < 7; ++j) {
                acc2[c][0] = fma2(w2a[j][0], pack2(nv[j + 1], nv[j + 2]), acc2[c][0]);
                acc2[c][1] = fma2(w2a[j][1], pack2(nv[j + 3], nv[j + 4]), acc2[c][1]);
            }
        }
    }

    float ws[4];
    unpack2(ws2[0], ws[0], ws[1]); unpack2(ws2[1], ws[2], ws[3]);
    float inv[4];
    #pragma unroll
    for (int p = 0; p < 4; ++p) inv[p] = 1.f / ws[p];

    float* ob = out + (long)bz * 3 * HW + ctr;
    #pragma unroll
    for (int c = 0; c < 3; ++c) {
        float a0, a1, a2, a3;
        unpack2(acc2[c][0], a0, a1); unpack2(acc2[c][1], a2, a3);
        float4 o; o.x = a0 * inv[0]; o.y = a1 * inv[1]; o.z = a2 * inv[2]; o.w = a3 * inv[3];
        *(float4*)(ob + c * HW) = o;
    }
}

// ---------------------------------------------------------------------------
// Border ring: 14288 px/batch, bounds-checked; blocks scheduled first.
// ---------------------------------------------------------------------------
__device__ __forceinline__ void border_path(const float* __restrict__ in,
                                            float* __restrict__ out,
                                            int bid, int bz)
{
    const int tid = threadIdx.y * 32 + threadIdx.x;
    int r = bid * 256 + tid;
    if (r >= 14288) return;
    int x, y;
    if (r < 3072)        { y = r >> 10;                x = r & 1023; }
    else if (r < 6144)   { r -= 3072;  y = 1021 + (r >> 10); x = r & 1023; }
    else if (r < 10216)  { r -= 6144;  y = 3 + (r >> 2);     x = r & 3; }
    else                 { r -= 10216; y = 3 + (r >> 2);     x = 1020 + (r & 3); }

    const float* base = in + (long)bz * CIN * HW;
    const long ctr = (long)y * Wd + x;

    float f[8], rp[8];
    #pragma unroll
    for (int c = 0; c < 8; ++c) {
        f[c] = base[c * HW + ctr];
        float pv = base[(8 + c) * HW + ctr];
        rp[c] = -(pv * pv);
    }
    float sv = base[16 * HW + ctr];
    float tv = base[17 * HW + ctr];
    const float sxl = -(sv * sv), syl = -(tv * tv);

    float a0 = 0.f, a1 = 0.f, a2 = 0.f, ws = 0.f;
    for (int i = 0; i < 7; ++i) {
        const int gy = y + i - 3;
        if (gy < 0 || gy >= Hd) continue;
        const float dy2 = (float)((i - 3) * (i - 3));
        for (int j = 0; j < 7; ++j) {
            const int gx = x + j - 3;
            if (gx < 0 || gx >= Wd) continue;
            const float dx2 = (float)((j - 3) * (j - 3));
            const float* q = base + (long)gy * Wd + gx;
            float fn[8];
            float lw = fmaf(sxl, dx2, syl * dy2);
            #pragma unroll
            for (int c = 0; c < 8; ++c) {
                fn[c] = q[c * HW];
                float d = fn[c] - f[c];
                lw = fmaf(rp[c], d * d, lw);
            }
            float w = __expf(lw);
            ws += w;
            a0 = fmaf(w, fn[0], a0);
            a1 = fmaf(w, fn[1], a1);
            a2 = fmaf(w, fn[2], a2);
        }
    }
    float* ob = out + (long)bz * 3 * HW + ctr;
    const float inv = 1.f / ws;
    ob[0]      = a0 * inv;
    ob[HW]     = a1 * inv;
    ob[2 * HW] = a2 * inv;
}

__global__ __launch_bounds__(256, 2)
void bilat_fused(const float* __restrict__ in, float* __restrict__ out)
{
    extern __shared__ __align__(16) float smem[];

    if (blockIdx.y < 7) {
        border_path(in, out, blockIdx.y * 8 + blockIdx.x, blockIdx.z);
    } else {
        interior_path(in, out, smem, (u64*)(smem + 8 * TCH),
                      blockIdx.x, blockIdx.y - 7, blockIdx.z);
    }
}

extern "C" void kernel_launch(void* const* d_in, const int* in_sizes, int n_in,
                              void* d_out, int out_size)
{
    const float* in = (const float*)d_in[0];
    float* out = (float*)d_out;

    cudaFuncSetAttribute(bilat_fused,
                         cudaFuncAttributeMaxDynamicSharedMemorySize, SMEM_BYTES);

    dim3 blk(32, 8, 1);
    // y: 7 border rows (56 blocks) + 128 interior rows (8 output rows each)
    dim3 grd(8, 7 + 128, 2);
    bilat_fused<<<grd, blk, SMEM_BYTES>>>(in, out);
}

// round 9
// speedup vs baseline: 2.0592x; 2.0592x over previous
#include <cuda_runtime.h>

constexpr int Wd = 1024, Hd = 1024;
constexpr long HW = (long)Wd * Hd;
constexpr int CIN = 18;
constexpr float L2E = 1.4426950408889634f;

// Tile: 8 ch x 10 rows x 136 cols = 43,520 B
constexpr int TP   = 136;
constexpr int TROW = 10;
constexpr int TCH  = TROW * TP;            // 1360
constexpr int SMEM_BYTES = 8 * TCH * 4;    // 43,520

using u64 = unsigned long long;

__device__ __forceinline__ u64 pack2(float lo, float hi) {
    u64 r; asm("mov.b64 %0,{%1,%2};" : "=l"(r) : "f"(lo), "f"(hi)); return r;
}
__device__ __forceinline__ void unpack2(u64 v, float& lo, float& hi) {
    asm("mov.b64 {%0,%1},%2;" : "=f"(lo), "=f"(hi) : "l"(v));
}
__device__ __forceinline__ u64 fma2(u64 a, u64 b, u64 c) {
    u64 d; asm("fma.rn.f32x2 %0,%1,%2,%3;" : "=l"(d) : "l"(a), "l"(b), "l"(c)); return d;
}
__device__ __forceinline__ u64 add2(u64 a, u64 b) {
    u64 d; asm("add.rn.f32x2 %0,%1,%2;" : "=l"(d) : "l"(a), "l"(b)); return d;
}
__device__ __forceinline__ float ex2(float x) {
    float r; asm("ex2.approx.f32 %0,%1;" : "=f"(r) : "f"(x)); return r;
}
__device__ __forceinline__ u64 bcast2(float x) {
    unsigned u = __float_as_uint(x); return ((u64)u << 32) | u;
}

// ---------------------------------------------------------------------------
// Interior: 4 px/thread, smem tile, f32x2 Horner. Channels processed in order
// 3..7,0,1,2; packed pairs of ch 0..2 stay live (kp) so there is NO separate
// accumulation reload pass. First channel peeled to init s2 from kd (no copy
// MOVs). Next channel's LDS.128s explicitly prefetched to hide LDS latency.
// ---------------------------------------------------------------------------
__device__ __forceinline__ void interior_path(const float* __restrict__ in,
                                              float* __restrict__ out,
                                              float* __restrict__ tile,
                                              int bx, int byi, int bz)
{
    const int g   = threadIdx.x;                 // 0..31
    const int ty  = threadIdx.y;                 // 0..3
    const int tid = ty * 32 + g;
    const int gxg = bx * 32 + g;
    const int x0  = 4 + gxg * 4;
    const int y   = 3 + byi * 4 + ty;

    const float* base = in + (long)bz * CIN * HW;

    // ---- Stage the 8 filterable channels (all 128 threads) ----
    {
        const int tx0 = bx * 128;
        const int gy0 = byi * 4;
        for (int idx = tid; idx < 2720; idx += 128) {      // 8*10*34 float4
            const int row = idx / 34;
            const int k   = idx - row * 34;
            const int c   = row / TROW;
            const int r   = row - c * TROW;
            int gx = tx0 + k * 4; if (gx > 1020) gx = 1020;  // clamped: unused
            int gy = gy0 + r;     if (gy > 1023) gy = 1023;  // clamped: unused
            float4 v = *(const float4*)(base + c * HW + (long)gy * Wd + gx);
            *(float4*)(tile + c * TCH + r * TP + k * 4) = v;
        }
    }
    __syncthreads();
    if (gxg > 253 || y > 1020) return;

    const long ctr = (long)y * Wd + x0;

    u64 rp2[8][2], mf2[8][2], K2[2], sxl2[2], syl2[2];
    {
        float Ks[4] = {0.f, 0.f, 0.f, 0.f};
        #pragma unroll
        for (int c = 0; c < 8; ++c) {
            float4 fv = *(const float4*)(tile + c * TCH + (ty + 3) * TP + g * 4 + 4);
            float4 pv = *(const float4*)(base + (8 + c) * HW + ctr);
            const float f4[4] = {fv.x, fv.y, fv.z, fv.w};
            const float p4[4] = {pv.x, pv.y, pv.z, pv.w};
            float rs[4], ms[4];
            #pragma unroll
            for (int p = 0; p < 4; ++p) {
                float r = -(p4[p] * p4[p]) * L2E;        // log2(e) folded in
                rs[p] = r;
                ms[p] = -2.f * r * f4[p];
                Ks[p] = fmaf(r * f4[p], f4[p], Ks[p]);
            }
            rp2[c][0] = pack2(rs[0], rs[1]); rp2[c][1] = pack2(rs[2], rs[3]);
            mf2[c][0] = pack2(ms[0], ms[1]); mf2[c][1] = pack2(ms[2], ms[3]);
        }
        K2[0] = pack2(Ks[0], Ks[1]); K2[1] = pack2(Ks[2], Ks[3]);
        float4 sv = *(const float4*)(base + 16 * HW + ctr);
        float4 tv = *(const float4*)(base + 17 * HW + ctr);
        sxl2[0] = pack2(-(sv.x*sv.x)*L2E, -(sv.y*sv.y)*L2E);
        sxl2[1] = pack2(-(sv.z*sv.z)*L2E, -(sv.w*sv.w)*L2E);
        syl2[0] = pack2(-(tv.x*tv.x)*L2E, -(tv.y*tv.y)*L2E);
        syl2[1] = pack2(-(tv.z*tv.z)*L2E, -(tv.w*tv.w)*L2E);
    }

    u64 acc2[3][2] = {}, ws2[2] = {};
    const int rowoff0 = ty * TP + g * 4;

    #pragma unroll 1       // keep body inside I$ L1.5
    for (int i = 0; i < 7; ++i) {
        const int ro = rowoff0 + i * TP;
        const u64 dyb = bcast2((float)((i - 3) * (i - 3)));
        const u64 kd0 = fma2(syl2[0], dyb, K2[0]);
        const u64 kd1 = fma2(syl2[1], dyb, K2[1]);

        u64 s2[7][2];
        u64 kp[3][9];      // packed pairs of output channels 0..2, kept live

        // Prefetch first channel (ch 3)
        float4 f0, f1, f2;
        {
            const float* r0 = tile + 3 * TCH + ro;
            f0 = *(const float4*)(r0);
            f1 = *(const float4*)(r0 + 4);
            f2 = *(const float4*)(r0 + 8);
        }

        // channel order: 3,4,5,6,7,0,1,2
        #pragma unroll
        for (int cc = 0; cc < 8; ++cc) {
            const float4 c0 = f0, c1 = f1, c2 = f2;
            if (cc < 7) {                      // prefetch next channel
                const int cn = (cc + 1 < 5) ? cc + 4 : cc - 4;
                const float* rn = tile + cn * TCH + ro;
                f0 = *(const float4*)(rn);
                f1 = *(const float4*)(rn + 4);
                f2 = *(const float4*)(rn + 8);
            }
            const int c = (cc < 5) ? cc + 3 : cc - 5;
            const float nv[12] = {c0.x, c0.y, c0.z, c0.w,
                                  c1.x, c1.y, c1.z, c1.w,
                                  c2.x, c2.y, c2.z, c2.w};
            u64 pr[9];
            #pragma unroll
            for (int k = 0; k < 9; ++k) pr[k] = pack2(nv[k + 1], nv[k + 2]);
            if (cc >= 5) {
                #pragma unroll
                for (int k = 0; k < 9; ++k) kp[cc - 5][k] = pr[k];
            }
            if (cc == 0) {
                #pragma unroll
                for (int j = 0; j < 7; ++j) {
                    s2[j][0] = fma2(pr[j],     fma2(rp2[c][0], pr[j],     mf2[c][0]), kd0);
                    s2[j][1] = fma2(pr[j + 2], fma2(rp2[c][1], pr[j + 2], mf2[c][1]), kd1);
                }
            } else {
                #pragma unroll
                for (int j = 0; j < 7; ++j) {
                    s2[j][0] = fma2(pr[j],     fma2(rp2[c][0], pr[j],     mf2[c][0]), s2[j][0]);
                    s2[j][1] = fma2(pr[j + 2], fma2(rp2[c][1], pr[j + 2], mf2[c][1]), s2[j][1]);
                }
            }
        }

        // Weights + fused accumulation (kp pairs still live — no reload)
        #pragma unroll
        for (int j = 0; j < 7; ++j) {
            const u64 dxb = bcast2((float)((j - 3) * (j - 3)));
            u64 lw0 = fma2(sxl2[0], dxb, s2[j][0]);
            u64 lw1 = fma2(sxl2[1], dxb, s2[j][1]);
            float a, b, c, d;
            unpack2(lw0, a, b); unpack2(lw1, c, d);
            u64 w0 = pack2(ex2(a), ex2(b));
            u64 w1 = pack2(ex2(c), ex2(d));
            ws2[0] = add2(ws2[0], w0);
            ws2[1] = add2(ws2[1], w1);
            #pragma unroll
            for (int ch = 0; ch < 3; ++ch) {
                acc2[ch][0] = fma2(w0, kp[ch][j],     acc2[ch][0]);
                acc2[ch][1] = fma2(w1, kp[ch][j + 2], acc2[ch][1]);
            }
        }
    }

    float ws[4];
    unpack2(ws2[0], ws[0], ws[1]); unpack2(ws2[1], ws[2], ws[3]);
    float inv[4];
    #pragma unroll
    for (int p = 0; p < 4; ++p) inv[p] = 1.f / ws[p];

    float* ob = out + (long)bz * 3 * HW + ctr;
    #pragma unroll
    for (int c = 0; c < 3; ++c) {
        float a0, a1, a2, a3;
        unpack2(acc2[c][0], a0, a1); unpack2(acc2[c][1], a2, a3);
        float4 o; o.x = a0 * inv[0]; o.y = a1 * inv[1]; o.z = a2 * inv[2]; o.w = a3 * inv[3];
        *(float4*)(ob + c * HW) = o;
    }
}

// ---------------------------------------------------------------------------
// Border ring: 14288 px/batch, bounds-checked; blocks scheduled first.
// ---------------------------------------------------------------------------
__device__ __forceinline__ void border_path(const float* __restrict__ in,
                                            float* __restrict__ out,
                                            int bid, int bz)
{
    const int tid = threadIdx.y * 32 + threadIdx.x;
    int r = bid * 128 + tid;
    if (r >= 14288) return;
    int x, y;
    if (r < 3072)        { y = r >> 10;                x = r & 1023; }
    else if (r < 6144)   { r -= 3072;  y = 1021 + (r >> 10); x = r & 1023; }
    else if (r < 10216)  { r -= 6144;  y = 3 + (r >> 2);     x = r & 3; }
    else                 { r -= 10216; y = 3 + (r >> 2);     x = 1020 + (r & 3); }

    const float* base = in + (long)bz * CIN * HW;
    const long ctr = (long)y * Wd + x;

    float f[8], rp[8];
    #pragma unroll
    for (int c = 0; c < 8; ++c) {
        f[c] = base[c * HW + ctr];
        float pv = base[(8 + c) * HW + ctr];
        rp[c] = -(pv * pv);
    }
    float sv = base[16 * HW + ctr];
    float tv = base[17 * HW + ctr];
    const float sxl = -(sv * sv), syl = -(tv * tv);

    float a0 = 0.f, a1 = 0.f, a2 = 0.f, ws = 0.f;
    for (int i = 0; i < 7; ++i) {
        const int gy = y + i - 3;
        if (gy < 0 || gy >= Hd) continue;
        const float dy2 = (float)((i - 3) * (i - 3));
        for (int j = 0; j < 7; ++j) {
            const int gx = x + j - 3;
            if (gx < 0 || gx >= Wd) continue;
            const float dx2 = (float)((j - 3) * (j - 3));
            const float* q = base + (long)gy * Wd + gx;
            float fn[8];
            float lw = fmaf(sxl, dx2, syl * dy2);
            #pragma unroll
            for (int c = 0; c < 8; ++c) {
                fn[c] = q[c * HW];
                float d = fn[c] - f[c];
                lw = fmaf(rp[c], d * d, lw);
            }
            float w = __expf(lw);
            ws += w;
            a0 = fmaf(w, fn[0], a0);
            a1 = fmaf(w, fn[1], a1);
            a2 = fmaf(w, fn[2], a2);
        }
    }
    float* ob = out + (long)bz * 3 * HW + ctr;
    const float inv = 1.f / ws;
    ob[0]      = a0 * inv;
    ob[HW]     = a1 * inv;
    ob[2 * HW] = a2 * inv;
}

__global__ __launch_bounds__(128, 2)   // 256-reg ceiling: no spills, free scheduling
void bilat_fused(const float* __restrict__ in, float* __restrict__ out)
{
    __shared__ __align__(16) float tile[8 * TCH];

    if (blockIdx.y < 14) {
        border_path(in, out, blockIdx.y * 8 + blockIdx.x, blockIdx.z);
    } else {
        interior_path(in, out, tile, blockIdx.x, blockIdx.y - 14, blockIdx.z);
    }
}

extern "C" void kernel_launch(void* const* d_in, const int* in_sizes, int n_in,
                              void* d_out, int out_size)
{
    const float* in = (const float*)d_in[0];
    float* out = (float*)d_out;

    dim3 blk(32, 4, 1);
    dim3 grd(8, 14 + 255, 2);   // 112 border blocks first, then 255x8 interior
    bilat_fused<<<grd, blk>>>(in, out);
}